// round 2
// baseline (speedup 1.0000x reference)
#include <cuda_runtime.h>
#include <cstddef>

#define TB 64
#define TT 1024
#define TI 64
#define TH 512
#define TR 8
#define TO 64

typedef unsigned long long ull;

// x-tilde states AFTER each step: g_xt[t*B*H + b*H + h] = x̃_{t+1}
__device__ float g_xt[(size_t)TT * TB * TH];
// 16 dot products evaluated at the state BEFORE step t: g_c1[(t*B+b)*16 + d]
// d = 0..7 -> r@M columns, d = 8..15 -> r@N columns
__device__ float g_c1[(size_t)TT * TB * 16];

__device__ __forceinline__ float fast_tanh(float x) {
    float y;
    asm("tanh.approx.f32 %0, %1;" : "=f"(y) : "f"(x));
    return y;
}

// accurate-cheap tanh: 1 - 2/(exp(2x)+1), via ex2.approx + rcp.approx (~1e-6 abs err)
__device__ __forceinline__ float acc_tanh(float x) {
    float e;
    asm("ex2.approx.f32 %0, %1;" : "=f"(e) : "f"(x * 2.8853900817779268f));
    float d;
    asm("rcp.approx.f32 %0, %1;" : "=f"(d) : "f"(e + 1.0f));
    return fmaf(-2.0f, d, 1.0f);
}

__device__ __forceinline__ void fma2(ull& acc, ull a, ull b) {
    asm("fma.rn.f32x2 %0, %1, %2, %0;" : "+l"(acc) : "l"(a), "l"(b));
}
__device__ __forceinline__ ull add2(ull a, ull b) {
    ull d;
    asm("add.rn.f32x2 %0, %1, %2;" : "=l"(d) : "l"(a), "l"(b));
    return d;
}
__device__ __forceinline__ ull dup2(float a) {
    ull d;
    asm("mov.b64 %0, {%1, %1};" : "=l"(d) : "f"(a));
    return d;
}
__device__ __forceinline__ void unpack2(ull v, float& lo, float& hi) {
    asm("mov.b64 {%0, %1}, %2;" : "=f"(lo), "=f"(hi) : "l"(v));
}

// ---------------------------------------------------------------------------
// Pass A: x̃ scan (no recurrent term) with fused input drive.
// Thread = one (b,h) strand. W_in row kept in 32 f32x2 registers.
// x̃ <- 0.8 x̃ + 0.05 n_t + 0.2 (W_in[h,:]·u[b,t,:] + b_in[h])
// Grid: 512 blocks (b*8+hq), block 64 threads.
// ---------------------------------------------------------------------------
__global__ void __launch_bounds__(64) k_scanA(const float* __restrict__ u,
                                              const float* __restrict__ x0,
                                              const float* __restrict__ noise,
                                              const float* __restrict__ W_in,
                                              const float* __restrict__ b_in)
{
    const int b  = blockIdx.x >> 3;
    const int hq = blockIdx.x & 7;
    const int h  = hq * 64 + threadIdx.x;

    ull W2[32];
    const ull* wrow = (const ull*)(W_in + (size_t)h * TI);
#pragma unroll
    for (int i = 0; i < 32; i++) W2[i] = wrow[i];
    const float bin = b_in[h];

    float x = x0[b * TH + h];
    const float* urow = u + (size_t)b * TT * TI;
    const size_t stride = (size_t)TB * TH;
    const size_t off = (size_t)b * TH + h;

    float n0 = noise[off];
    float n1 = noise[off + stride];
    float* xp = g_xt + off;

    for (int t = 0; t < TT; t++) {
        const ulonglong2* up = (const ulonglong2*)(urow + (size_t)t * TI);
        ull a0 = 0ull, a1 = 0ull, a2 = 0ull, a3 = 0ull;
#pragma unroll
        for (int q = 0; q < 16; q += 4) {
            ulonglong2 v0 = up[q + 0];
            ulonglong2 v1 = up[q + 1];
            ulonglong2 v2 = up[q + 2];
            ulonglong2 v3 = up[q + 3];
            fma2(a0, v0.x, W2[2 * q + 0]); fma2(a1, v0.y, W2[2 * q + 1]);
            fma2(a2, v1.x, W2[2 * q + 2]); fma2(a3, v1.y, W2[2 * q + 3]);
            fma2(a0, v2.x, W2[2 * q + 4]); fma2(a1, v2.y, W2[2 * q + 5]);
            fma2(a2, v3.x, W2[2 * q + 6]); fma2(a3, v3.y, W2[2 * q + 7]);
        }
        ull s = add2(add2(a0, a1), add2(a2, a3));
        float lo, hi;
        unpack2(s, lo, hi);
        float inp = lo + hi + bin;

        x = fmaf(0.8f, x, fmaf(0.05f, n0, 0.2f * inp));
        xp[(size_t)t * stride] = x;

        n0 = n1;
        if (t + 2 < TT) n1 = noise[off + (size_t)(t + 2) * stride];
    }
}

// ---------------------------------------------------------------------------
// Pass B: for every row m = t*B + b (state BEFORE step t), compute
//   c1[m, d] = sum_h tanh(x̃_t[h]) * C_d[h]     (C_0..7 = M cols, C_8..15 = N cols)
// Block: 256 threads = 8 warps = 2 row-slots x 4 dot-groups (4 dots/warp, coefs
// in registers). Each warp processes 64 rows sequentially. Grid: 512 blocks.
// ---------------------------------------------------------------------------
__global__ void __launch_bounds__(256) k_rec(const float* __restrict__ x0,
                                             const float* __restrict__ Mw,
                                             const float* __restrict__ Nw)
{
    const int tid     = threadIdx.x;
    const int wid     = tid >> 5;
    const int lane    = tid & 31;
    const int rowslot = wid >> 2;     // 0..1
    const int jg      = wid & 3;      // 0..3 (4 dots each)

    // coefficient registers: 4 dots x 16 h-slices
    const float* base = (jg < 2) ? Mw : Nw;
    const int joff = (jg & 1) * 4;
    float4 cf[16];
#pragma unroll
    for (int s = 0; s < 16; s++) {
        int hh = lane + 32 * s;
        cf[s] = *(const float4*)(base + (size_t)hh * TR + joff);
    }

    const int rowbase = blockIdx.x * 128;

    for (int it = 0; it < 64; it++) {
        const int m = rowbase + it * 2 + rowslot;
        const float* src = (m < TB) ? (x0 + (size_t)m * TH)
                                    : (g_xt + (size_t)(m - TB) * TH);
        float s0 = 0.f, s1 = 0.f, s2 = 0.f, s3 = 0.f;
#pragma unroll
        for (int s = 0; s < 16; s++) {
            float r = fast_tanh(src[lane + 32 * s]);
            s0 = fmaf(r, cf[s].x, s0);
            s1 = fmaf(r, cf[s].y, s1);
            s2 = fmaf(r, cf[s].z, s2);
            s3 = fmaf(r, cf[s].w, s3);
        }
#pragma unroll
        for (int o = 16; o; o >>= 1) {
            s0 += __shfl_xor_sync(0xffffffffu, s0, o);
            s1 += __shfl_xor_sync(0xffffffffu, s1, o);
            s2 += __shfl_xor_sync(0xffffffffu, s2, o);
            s3 += __shfl_xor_sync(0xffffffffu, s3, o);
        }
        if (lane == 0) {
            float4 v = make_float4(s0, s1, s2, s3);
            *(float4*)(g_c1 + (size_t)m * 16 + jg * 4) = v;
        }
    }
}

// ---------------------------------------------------------------------------
// Pass C: exact first-order correction scan + final trajectory assembly.
//   rec_t[h] = sum_j (c1[t,b,j] * c1[t,b,j+8]) * L[h,j]
//   eps <- 0.8 eps + (TAU/H^2) * rec_t ;  traj[b,t,h] = x̃[t,b,h] + eps
// Grid: 256 blocks (b*4+hq), block 128 threads.
// ---------------------------------------------------------------------------
__global__ void __launch_bounds__(128) k_scanC(const float* __restrict__ L,
                                               float* __restrict__ traj,
                                               float* __restrict__ xlast)
{
    const int b  = blockIdx.x >> 2;
    const int hq = blockIdx.x & 3;
    const int h  = hq * 128 + threadIdx.x;

    float4 L0 = *(const float4*)(L + (size_t)h * TR);
    float4 L1 = *(const float4*)(L + (size_t)h * TR + 4);

    const float KC = 0.2f / ((float)TH * (float)TH);
    const size_t stride = (size_t)TB * TH;
    const size_t off = (size_t)b * TH + h;

    float eps = 0.f;
    const float* c1p = g_c1 + (size_t)b * 16;
    const size_t c1s = (size_t)TB * 16;

    // prefetch state t=0 c1 row and x̃
    float4 ca = *(const float4*)(c1p + 0);
    float4 cb = *(const float4*)(c1p + 4);
    float4 cc = *(const float4*)(c1p + 8);
    float4 cd = *(const float4*)(c1p + 12);
    float xa = g_xt[off];
    float xb = g_xt[off + stride];

    float* tp = traj + ((size_t)b * TT) * TH + h;
    float x = 0.f;

    for (int t = 0; t < TT; t++) {
        float rec = 0.f;
        rec = fmaf(ca.x * cc.x, L0.x, rec);
        rec = fmaf(ca.y * cc.y, L0.y, rec);
        rec = fmaf(ca.z * cc.z, L0.z, rec);
        rec = fmaf(ca.w * cc.w, L0.w, rec);
        rec = fmaf(cb.x * cd.x, L1.x, rec);
        rec = fmaf(cb.y * cd.y, L1.y, rec);
        rec = fmaf(cb.z * cd.z, L1.z, rec);
        rec = fmaf(cb.w * cd.w, L1.w, rec);

        eps = fmaf(KC, rec, 0.8f * eps);
        x = xa + eps;
        tp[(size_t)t * TH] = x;

        // rotate prefetches
        xa = xb;
        if (t + 2 < TT) xb = g_xt[off + (size_t)(t + 2) * stride];
        if (t + 1 < TT) {
            const float* nr = c1p + (size_t)(t + 1) * c1s;
            ca = *(const float4*)(nr + 0);
            cb = *(const float4*)(nr + 4);
            cc = *(const float4*)(nr + 8);
            cd = *(const float4*)(nr + 12);
        }
    }
    xlast[b * TH + h] = x;
}

// ---------------------------------------------------------------------------
// k_out: out[m, o] = b_out[o] + sum_h tanh(traj[m, h]) * W_out[o, h]
// 64x64 tile, K=512 in 8 chunks. f32x2-packed over output pairs.
// ---------------------------------------------------------------------------
__global__ void __launch_bounds__(256) k_out(const float* __restrict__ traj,
                                             const float* __restrict__ W_out,
                                             const float* __restrict__ b_out,
                                             float* __restrict__ outp)
{
    __shared__ __align__(16) float at[64 * 64];    // tanh(traj) tile, [k][row^sw]
    __shared__ __align__(16) float bs2[64 * 64];   // W_out tile,     [k][o^sw]
    const int bm  = blockIdx.x;
    const int tid = threadIdx.x;
    const int tx = tid & 15;        // o sub-block (4 outputs)
    const int ty = tid >> 4;        // row sub-block (4 rows)

    ull acc[4][2];
#pragma unroll
    for (int i = 0; i < 4; i++) { acc[i][0] = 0ull; acc[i][1] = 0ull; }

    for (int kc = 0; kc < 8; kc++) {
        __syncthreads();
#pragma unroll
        for (int s = 0; s < 16; s++) {
            int i = tid + s * 256;
            int r = i >> 6;
            int k = i & 63;
            int sw = (k & 15) << 2;
            float tv = traj[((size_t)(bm * 64 + r)) * TH + kc * 64 + k];
            at[k * 64 + (r ^ sw)]  = acc_tanh(tv);
            bs2[k * 64 + (r ^ sw)] = W_out[(size_t)r * TH + kc * 64 + k];
        }
        __syncthreads();
#pragma unroll
        for (int k = 0; k < 64; k++) {
            int sw = (k & 15) << 2;
            float4 a = *(const float4*)&at[k * 64 + ((ty * 4) ^ sw)];
            ulonglong2 w2 = *(const ulonglong2*)&bs2[k * 64 + ((tx * 4) ^ sw)];
            ull d0 = dup2(a.x), d1 = dup2(a.y), d2 = dup2(a.z), d3 = dup2(a.w);
            fma2(acc[0][0], d0, w2.x); fma2(acc[0][1], d0, w2.y);
            fma2(acc[1][0], d1, w2.x); fma2(acc[1][1], d1, w2.y);
            fma2(acc[2][0], d2, w2.x); fma2(acc[2][1], d2, w2.y);
            fma2(acc[3][0], d3, w2.x); fma2(acc[3][1], d3, w2.y);
        }
    }

    const int o0 = tx * 4;
    float4 bias = *(const float4*)&b_out[o0];
#pragma unroll
    for (int i = 0; i < 4; i++) {
        int m = bm * 64 + ty * 4 + i;
        float v0, v1, v2, v3;
        unpack2(acc[i][0], v0, v1);
        unpack2(acc[i][1], v2, v3);
        float4 o;
        o.x = v0 + bias.x;
        o.y = v1 + bias.y;
        o.z = v2 + bias.z;
        o.w = v3 + bias.w;
        *(float4*)&outp[(size_t)m * TO + o0] = o;
    }
}

// ---------------------------------------------------------------------------
// Launcher. Inputs: u, x0, noise, L, M, N, W_in, b_in, W_out, b_out.
// Output buffer: [output | x_last | traj].
// ---------------------------------------------------------------------------
extern "C" void kernel_launch(void* const* d_in, const int* in_sizes, int n_in,
                              void* d_out, int out_size)
{
    (void)in_sizes; (void)n_in; (void)out_size;
    const float* u     = (const float*)d_in[0];
    const float* x0    = (const float*)d_in[1];
    const float* noise = (const float*)d_in[2];
    const float* L     = (const float*)d_in[3];
    const float* Mw    = (const float*)d_in[4];
    const float* Nw    = (const float*)d_in[5];
    const float* W_in  = (const float*)d_in[6];
    const float* b_in  = (const float*)d_in[7];
    const float* W_out = (const float*)d_in[8];
    const float* b_out = (const float*)d_in[9];

    float* outp  = (float*)d_out;
    float* xlast = outp + (size_t)TB * TT * TO;
    float* traj  = xlast + (size_t)TB * TH;

    k_scanA<<<512, 64>>>(u, x0, noise, W_in, b_in);
    k_rec<<<512, 256>>>(x0, Mw, Nw);
    k_scanC<<<256, 128>>>(L, traj, xlast);
    k_out<<<(TB * TT) / 64, 256>>>(traj, W_out, b_out, outp);
}

// round 3
// speedup vs baseline: 1.9592x; 1.9592x over previous
#include <cuda_runtime.h>
#include <cstddef>

#define TB 64
#define TT 1024
#define TI 64
#define TH 512
#define TR 8
#define TO 64

typedef unsigned long long ull;

// input drive [T,B,H]
__device__ float g_inp[(size_t)TT * TB * TH];
// x-tilde AFTER step t (no-rec scan): g_xt[(t*B + b)*H + h]
__device__ float g_xt[(size_t)TT * TB * TH];
// 16 dots at state BEFORE step t: g_c1[(t*B+b)*16 + d]; d<8: r@M, d>=8: r@N
__device__ float g_c1[(size_t)TT * TB * 16];
// scanned products, indexed by output row m=b*T+t: g_q[m*8 + j]
__device__ float g_q[(size_t)TB * TT * 8];

__device__ __forceinline__ float fast_tanh(float x) {
    float y;
    asm("tanh.approx.f32 %0, %1;" : "=f"(y) : "f"(x));
    return y;
}
__device__ __forceinline__ float acc_tanh(float x) {
    float e;
    asm("ex2.approx.f32 %0, %1;" : "=f"(e) : "f"(x * 2.8853900817779268f));
    float d;
    asm("rcp.approx.f32 %0, %1;" : "=f"(d) : "f"(e + 1.0f));
    return fmaf(-2.0f, d, 1.0f);
}
__device__ __forceinline__ void fma2(ull& acc, ull a, ull b) {
    asm("fma.rn.f32x2 %0, %1, %2, %0;" : "+l"(acc) : "l"(a), "l"(b));
}
__device__ __forceinline__ ull dup2(float a) {
    ull d;
    asm("mov.b64 %0, {%1, %1};" : "=l"(d) : "f"(a));
    return d;
}
__device__ __forceinline__ void unpack2(ull v, float& lo, float& hi) {
    asm("mov.b64 {%0, %1}, %2;" : "=f"(lo), "=f"(hi) : "l"(v));
}

// ---------------------------------------------------------------------------
// K1: g_inp[(t*B+b)*H + h] = b_in[h] + u[b,t,:]·W_in[h,:]   (f32x2-packed GEMM)
// ---------------------------------------------------------------------------
__global__ void __launch_bounds__(256) k_inp(const float* __restrict__ u,
                                             const float* __restrict__ W_in,
                                             const float* __restrict__ b_in)
{
    __shared__ __align__(16) float as[64 * 64];
    __shared__ __align__(16) float bs[64 * 64];
    const int t   = blockIdx.x;
    const int bn  = blockIdx.y;
    const int tid = threadIdx.x;

#pragma unroll
    for (int s = 0; s < 16; s++) {
        int i = tid + s * 256;
        int r = i >> 6;
        int k = i & 63;
        int sw = (k & 15) << 2;
        as[k * 64 + (r ^ sw)] = u[((size_t)((r << 10) + t)) * 64 + k];
        bs[k * 64 + (r ^ sw)] = W_in[(size_t)(bn * 64 + r) * 64 + k];
    }
    __syncthreads();

    const int tx = tid & 15;
    const int ty = tid >> 4;
    ull acc[4][2];
#pragma unroll
    for (int i = 0; i < 4; i++) { acc[i][0] = 0ull; acc[i][1] = 0ull; }

#pragma unroll
    for (int k = 0; k < 64; k++) {
        int sw = (k & 15) << 2;
        float4 a = *(const float4*)&as[k * 64 + ((ty * 4) ^ sw)];
        ulonglong2 w2 = *(const ulonglong2*)&bs[k * 64 + ((tx * 4) ^ sw)];
        ull d0 = dup2(a.x), d1 = dup2(a.y), d2 = dup2(a.z), d3 = dup2(a.w);
        fma2(acc[0][0], d0, w2.x); fma2(acc[0][1], d0, w2.y);
        fma2(acc[1][0], d1, w2.x); fma2(acc[1][1], d1, w2.y);
        fma2(acc[2][0], d2, w2.x); fma2(acc[2][1], d2, w2.y);
        fma2(acc[3][0], d3, w2.x); fma2(acc[3][1], d3, w2.y);
    }

    const int h0 = bn * 64 + tx * 4;
    float4 bias = *(const float4*)&b_in[h0];
#pragma unroll
    for (int i = 0; i < 4; i++) {
        int m = (t << 6) + ty * 4 + i;
        float v0, v1, v2, v3;
        unpack2(acc[i][0], v0, v1);
        unpack2(acc[i][1], v2, v3);
        float4 o;
        o.x = v0 + bias.x; o.y = v1 + bias.y;
        o.z = v2 + bias.z; o.w = v3 + bias.w;
        *(float4*)&g_inp[(size_t)m * TH + h0] = o;
    }
}

// ---------------------------------------------------------------------------
// K2: chunked elementwise scan  x̃ <- 0.8 x̃ + 0.05 n + 0.2 inp
// grid (128, 4): x = b*2+hq, y = chunk of 256 t (chunks>0 warm in 128 steps).
// ---------------------------------------------------------------------------
__global__ void __launch_bounds__(256) k_scanA(const float* __restrict__ noise,
                                               const float* __restrict__ x0)
{
    const int b  = blockIdx.x >> 1;
    const int h  = (blockIdx.x & 1) * 256 + threadIdx.x;
    const int chunk = blockIdx.y;

    const int t0 = chunk * 256;
    const int tstart = (chunk == 0) ? 0 : t0 - 128;
    const int tend = t0 + 256;

    float x = (chunk == 0) ? x0[b * TH + h] : 0.f;

    const size_t stride = (size_t)TB * TH;
    const size_t off = (size_t)b * TH + h;

    float i0 = g_inp[off + (size_t)tstart * stride];
    float n0 = noise[off + (size_t)tstart * stride];
    float i1 = g_inp[off + (size_t)(tstart + 1) * stride];
    float n1 = noise[off + (size_t)(tstart + 1) * stride];

    for (int t = tstart; t < tend; t++) {
        x = fmaf(0.8f, x, fmaf(0.05f, n0, 0.2f * i0));
        if (t >= t0) g_xt[off + (size_t)t * stride] = x;
        i0 = i1; n0 = n1;
        if (t + 2 < tend) {
            size_t o2 = off + (size_t)(t + 2) * stride;
            i1 = g_inp[o2];
            n1 = noise[o2];
        }
    }
}

// ---------------------------------------------------------------------------
// K3: c1[m,d] = sum_h tanh(state_m[h]) * C_d[h],  m = t*B+b, state entering t.
// Block 256 = 2 rowslots x 4 dot-groups (4 dots/warp, coefs in regs), 32 iters.
// ---------------------------------------------------------------------------
__global__ void __launch_bounds__(256) k_rec(const float* __restrict__ x0,
                                             const float* __restrict__ Mw,
                                             const float* __restrict__ Nw)
{
    const int tid     = threadIdx.x;
    const int wid     = tid >> 5;
    const int lane    = tid & 31;
    const int rowslot = wid >> 2;
    const int jg      = wid & 3;

    const float* base = (jg < 2) ? Mw : Nw;
    const int joff = (jg & 1) * 4;
    float4 cf[16];
#pragma unroll
    for (int s = 0; s < 16; s++) {
        int hh = lane + 32 * s;
        cf[s] = *(const float4*)(base + (size_t)hh * TR + joff);
    }

    const int rowbase = blockIdx.x * 64;

    for (int it = 0; it < 32; it++) {
        const int m = rowbase + it * 2 + rowslot;
        const float* src = (m < TB) ? (x0 + (size_t)m * TH)
                                    : (g_xt + (size_t)(m - TB) * TH);
        float s0 = 0.f, s1 = 0.f, s2 = 0.f, s3 = 0.f;
#pragma unroll
        for (int s = 0; s < 16; s++) {
            float r = fast_tanh(src[lane + 32 * s]);
            s0 = fmaf(r, cf[s].x, s0);
            s1 = fmaf(r, cf[s].y, s1);
            s2 = fmaf(r, cf[s].z, s2);
            s3 = fmaf(r, cf[s].w, s3);
        }
#pragma unroll
        for (int o = 16; o; o >>= 1) {
            s0 += __shfl_xor_sync(0xffffffffu, s0, o);
            s1 += __shfl_xor_sync(0xffffffffu, s1, o);
            s2 += __shfl_xor_sync(0xffffffffu, s2, o);
            s3 += __shfl_xor_sync(0xffffffffu, s3, o);
        }
        if (lane == 0)
            *(float4*)(g_c1 + (size_t)m * 16 + jg * 4) = make_float4(s0, s1, s2, s3);
    }
}

// ---------------------------------------------------------------------------
// K4: rank-8 scalar scan  q_j(t) = 0.8 q_j(t-1) + c1[t,j]*c1[t,j+8]
// grid 16 blocks x 128 threads: chunk = blk>>2 (256 t each, 128 warm),
// thread = (b within sub-group, j).
// ---------------------------------------------------------------------------
__global__ void __launch_bounds__(128) k_qscan()
{
    const int chunk = blockIdx.x >> 2;
    const int sub   = blockIdx.x & 3;
    const int b     = sub * 16 + (threadIdx.x >> 3);
    const int j     = threadIdx.x & 7;

    const int t0 = chunk * 256;
    const int tstart = (chunk == 0) ? 0 : t0 - 128;
    const int tend = t0 + 256;

    float q = 0.f;

    size_t m0 = (size_t)(tstart * TB + b) * 16 + j;
    float pa = g_c1[m0];
    float pb = g_c1[m0 + 8];
    size_t m1 = m0 + (size_t)TB * 16;
    float pa1 = g_c1[m1];
    float pb1 = g_c1[m1 + 8];

    for (int t = tstart; t < tend; t++) {
        q = fmaf(0.8f, q, pa * pb);
        if (t >= t0) g_q[((size_t)b * TT + t) * 8 + j] = q;
        pa = pa1; pb = pb1;
        if (t + 2 < tend) {
            size_t m2 = (size_t)((t + 2) * TB + b) * 16 + j;
            pa1 = g_c1[m2];
            pb1 = g_c1[m2 + 8];
        }
    }
}

// ---------------------------------------------------------------------------
// K5: fused traj assembly + readout GEMM.
//   traj[m,h] = x̃[t,b,h] + KC * sum_j L[h,j] q[m,j]     (m = b*T + t)
//   out[m,o]  = b_out[o] + sum_h tanh(traj[m,h]) * W_out[o,h]
//   xlast[b,h] = traj at t = T-1.
// ---------------------------------------------------------------------------
__global__ void __launch_bounds__(256) k_out(const float* __restrict__ W_out,
                                             const float* __restrict__ b_out,
                                             const float* __restrict__ L,
                                             float* __restrict__ outp,
                                             float* __restrict__ traj,
                                             float* __restrict__ xlast)
{
    __shared__ __align__(16) float at[64 * 64];    // [k][row^sw]
    __shared__ __align__(16) float bs2[64 * 64];   // [k][o^sw]
    const int bm  = blockIdx.x;
    const int tid = threadIdx.x;
    const int tx = tid & 15;
    const int ty = tid >> 4;
    const int kq = tid & 63;            // this thread's k (constant over s)
    const int sw = (kq & 15) << 2;
    const float KC = 0.2f / ((float)TH * (float)TH);

    ull acc[4][2];
#pragma unroll
    for (int i = 0; i < 4; i++) { acc[i][0] = 0ull; acc[i][1] = 0ull; }

    for (int kc = 0; kc < 8; kc++) {
        const int h = kc * 64 + kq;
        float4 L0 = *(const float4*)(L + (size_t)h * TR);
        float4 L1 = *(const float4*)(L + (size_t)h * TR + 4);
        __syncthreads();
#pragma unroll
        for (int s = 0; s < 16; s++) {
            int r = (tid >> 6) + s * 4;          // row within tile
            int m = bm * 64 + r;                 // global row = b*T + t
            int t = m & (TT - 1);
            int b = m >> 10;
            float xt = g_xt[((size_t)(t * TB + b)) * TH + h];
            const float* qp = g_q + (size_t)m * 8;
            float4 q0 = *(const float4*)qp;
            float4 q1 = *(const float4*)(qp + 4);
            float e = L0.x * q0.x;
            e = fmaf(L0.y, q0.y, e);
            e = fmaf(L0.z, q0.z, e);
            e = fmaf(L0.w, q0.w, e);
            e = fmaf(L1.x, q1.x, e);
            e = fmaf(L1.y, q1.y, e);
            e = fmaf(L1.z, q1.z, e);
            e = fmaf(L1.w, q1.w, e);
            float tv = fmaf(KC, e, xt);
            traj[(size_t)m * TH + h] = tv;
            if (t == TT - 1) xlast[(size_t)b * TH + h] = tv;
            at[kq * 64 + (r ^ sw)]  = acc_tanh(tv);
            bs2[kq * 64 + (r ^ sw)] = W_out[(size_t)r * TH + h];
        }
        __syncthreads();
#pragma unroll
        for (int k = 0; k < 64; k++) {
            int swk = (k & 15) << 2;
            float4 a = *(const float4*)&at[k * 64 + ((ty * 4) ^ swk)];
            ulonglong2 w2 = *(const ulonglong2*)&bs2[k * 64 + ((tx * 4) ^ swk)];
            ull d0 = dup2(a.x), d1 = dup2(a.y), d2 = dup2(a.z), d3 = dup2(a.w);
            fma2(acc[0][0], d0, w2.x); fma2(acc[0][1], d0, w2.y);
            fma2(acc[1][0], d1, w2.x); fma2(acc[1][1], d1, w2.y);
            fma2(acc[2][0], d2, w2.x); fma2(acc[2][1], d2, w2.y);
            fma2(acc[3][0], d3, w2.x); fma2(acc[3][1], d3, w2.y);
        }
    }

    const int o0 = tx * 4;
    float4 bias = *(const float4*)&b_out[o0];
#pragma unroll
    for (int i = 0; i < 4; i++) {
        int m = bm * 64 + ty * 4 + i;
        float v0, v1, v2, v3;
        unpack2(acc[i][0], v0, v1);
        unpack2(acc[i][1], v2, v3);
        float4 o;
        o.x = v0 + bias.x; o.y = v1 + bias.y;
        o.z = v2 + bias.z; o.w = v3 + bias.w;
        *(float4*)&outp[(size_t)m * TO + o0] = o;
    }
}

// ---------------------------------------------------------------------------
// Launcher. Inputs: u, x0, noise, L, M, N, W_in, b_in, W_out, b_out.
// Output: [output | x_last | traj].
// ---------------------------------------------------------------------------
extern "C" void kernel_launch(void* const* d_in, const int* in_sizes, int n_in,
                              void* d_out, int out_size)
{
    (void)in_sizes; (void)n_in; (void)out_size;
    const float* u     = (const float*)d_in[0];
    const float* x0    = (const float*)d_in[1];
    const float* noise = (const float*)d_in[2];
    const float* L     = (const float*)d_in[3];
    const float* Mw    = (const float*)d_in[4];
    const float* Nw    = (const float*)d_in[5];
    const float* W_in  = (const float*)d_in[6];
    const float* b_in  = (const float*)d_in[7];
    const float* W_out = (const float*)d_in[8];
    const float* b_out = (const float*)d_in[9];

    float* outp  = (float*)d_out;
    float* xlast = outp + (size_t)TB * TT * TO;
    float* traj  = xlast + (size_t)TB * TH;

    dim3 g1(TT, TH / 64);
    k_inp<<<g1, 256>>>(u, W_in, b_in);
    k_scanA<<<dim3(128, 4), 256>>>(noise, x0);
    k_rec<<<1024, 256>>>(x0, Mw, Nw);
    k_qscan<<<16, 128>>>();
    k_out<<<(TB * TT) / 64, 256>>>(W_out, b_out, L, outp, traj, xlast);
}

// round 4
// speedup vs baseline: 2.6098x; 1.3321x over previous
#include <cuda_runtime.h>
#include <cstddef>

#define TB 64
#define TT 1024
#define TI 64
#define TH 512
#define TR 8
#define TO 64

typedef unsigned long long ull;

// combined drive d = 0.05*noise + 0.2*(u@W_in^T + b_in), layout [T,B,H]
__device__ float g_drv[(size_t)TT * TB * TH];
// x-tilde AFTER step t (no-rec scan): g_xt[(t*B + b)*H + h]
__device__ float g_xt[(size_t)TT * TB * TH];
// 16 dots at state BEFORE step t: g_c1[(t*B+b)*16 + d]; d<8: r@M, d>=8: r@N
__device__ float g_c1[(size_t)TT * TB * 16];
// scanned products, indexed by output row m=b*T+t: g_q[m*8 + j]
__device__ float g_q[(size_t)TB * TT * 8];

__device__ __forceinline__ float fast_tanh(float x) {
    float y;
    asm("tanh.approx.f32 %0, %1;" : "=f"(y) : "f"(x));
    return y;
}
__device__ __forceinline__ float acc_tanh(float x) {
    float e;
    asm("ex2.approx.f32 %0, %1;" : "=f"(e) : "f"(x * 2.8853900817779268f));
    float d;
    asm("rcp.approx.f32 %0, %1;" : "=f"(d) : "f"(e + 1.0f));
    return fmaf(-2.0f, d, 1.0f);
}
__device__ __forceinline__ void fma2(ull& acc, ull a, ull b) {
    asm("fma.rn.f32x2 %0, %1, %2, %0;" : "+l"(acc) : "l"(a), "l"(b));
}
__device__ __forceinline__ ull dup2(float a) {
    ull d;
    asm("mov.b64 %0, {%1, %1};" : "=l"(d) : "f"(a));
    return d;
}
__device__ __forceinline__ void unpack2(ull v, float& lo, float& hi) {
    asm("mov.b64 {%0, %1}, %2;" : "=f"(lo), "=f"(hi) : "l"(v));
}

// ---------------------------------------------------------------------------
// K1: g_drv[(t*B+b)*H+h] = 0.05*noise + 0.2*(b_in[h] + u[b,t,:]·W_in[h,:])
// ---------------------------------------------------------------------------
__global__ void __launch_bounds__(256) k_inp(const float* __restrict__ u,
                                             const float* __restrict__ W_in,
                                             const float* __restrict__ b_in,
                                             const float* __restrict__ noise)
{
    __shared__ __align__(16) float as[64 * 64];
    __shared__ __align__(16) float bs[64 * 64];
    const int t   = blockIdx.x;
    const int bn  = blockIdx.y;
    const int tid = threadIdx.x;

#pragma unroll
    for (int s = 0; s < 16; s++) {
        int i = tid + s * 256;
        int r = i >> 6;
        int k = i & 63;
        int sw = (k & 15) << 2;
        as[k * 64 + (r ^ sw)] = u[((size_t)((r << 10) + t)) * 64 + k];
        bs[k * 64 + (r ^ sw)] = W_in[(size_t)(bn * 64 + r) * 64 + k];
    }
    __syncthreads();

    const int tx = tid & 15;
    const int ty = tid >> 4;
    ull acc[4][2];
#pragma unroll
    for (int i = 0; i < 4; i++) { acc[i][0] = 0ull; acc[i][1] = 0ull; }

#pragma unroll
    for (int k = 0; k < 64; k++) {
        int sw = (k & 15) << 2;
        float4 a = *(const float4*)&as[k * 64 + ((ty * 4) ^ sw)];
        ulonglong2 w2 = *(const ulonglong2*)&bs[k * 64 + ((tx * 4) ^ sw)];
        ull d0 = dup2(a.x), d1 = dup2(a.y), d2 = dup2(a.z), d3 = dup2(a.w);
        fma2(acc[0][0], d0, w2.x); fma2(acc[0][1], d0, w2.y);
        fma2(acc[1][0], d1, w2.x); fma2(acc[1][1], d1, w2.y);
        fma2(acc[2][0], d2, w2.x); fma2(acc[2][1], d2, w2.y);
        fma2(acc[3][0], d3, w2.x); fma2(acc[3][1], d3, w2.y);
    }

    const int h0 = bn * 64 + tx * 4;
    float4 bias = *(const float4*)&b_in[h0];
#pragma unroll
    for (int i = 0; i < 4; i++) {
        int m = (t << 6) + ty * 4 + i;
        float v0, v1, v2, v3;
        unpack2(acc[i][0], v0, v1);
        unpack2(acc[i][1], v2, v3);
        float4 noi = *(const float4*)&noise[(size_t)m * TH + h0];
        float4 o;
        o.x = fmaf(0.05f, noi.x, 0.2f * (v0 + bias.x));
        o.y = fmaf(0.05f, noi.y, 0.2f * (v1 + bias.y));
        o.z = fmaf(0.05f, noi.z, 0.2f * (v2 + bias.z));
        o.w = fmaf(0.05f, noi.w, 0.2f * (v3 + bias.w));
        *(float4*)&g_drv[(size_t)m * TH + h0] = o;
    }
}

// ---------------------------------------------------------------------------
// K2: chunked elementwise scan  x̃ <- 0.8 x̃ + d,  8-deep prefetch ring.
// grid (128, 4): x = b*2+hq, y = chunk of 256 t (chunks>0 warm in 128 steps).
// ---------------------------------------------------------------------------
__global__ void __launch_bounds__(256) k_scanA(const float* __restrict__ x0)
{
    const int b  = blockIdx.x >> 1;
    const int h  = (blockIdx.x & 1) * 256 + threadIdx.x;
    const int chunk = blockIdx.y;

    const int t0 = chunk * 256;
    const int tstart = (chunk == 0) ? 0 : t0 - 128;
    const int tend = t0 + 256;

    float x = (chunk == 0) ? x0[b * TH + h] : 0.f;

    const size_t stride = (size_t)TB * TH;
    const size_t off = (size_t)b * TH + h;
    const float* dp = g_drv + off;
    float* xp = g_xt + off;

    float d[8];
#pragma unroll
    for (int p = 0; p < 8; p++)
        d[p] = dp[(size_t)(tstart + p) * stride];

    for (int t = tstart; t < tend; t += 8) {
#pragma unroll
        for (int k = 0; k < 8; k++) {
            x = fmaf(0.8f, x, d[k]);
            if (t + k >= t0) xp[(size_t)(t + k) * stride] = x;
            if (t + k + 8 < tend) d[k] = dp[(size_t)(t + k + 8) * stride];
        }
    }
}

// ---------------------------------------------------------------------------
// K3: c1[m,d] = sum_h tanh(state_m[h]) * C_d[h],  m = t*B+b, state entering t.
// ---------------------------------------------------------------------------
__global__ void __launch_bounds__(256) k_rec(const float* __restrict__ x0,
                                             const float* __restrict__ Mw,
                                             const float* __restrict__ Nw)
{
    const int tid     = threadIdx.x;
    const int wid     = tid >> 5;
    const int lane    = tid & 31;
    const int rowslot = wid >> 2;
    const int jg      = wid & 3;

    const float* base = (jg < 2) ? Mw : Nw;
    const int joff = (jg & 1) * 4;
    float4 cf[16];
#pragma unroll
    for (int s = 0; s < 16; s++) {
        int hh = lane + 32 * s;
        cf[s] = *(const float4*)(base + (size_t)hh * TR + joff);
    }

    const int rowbase = blockIdx.x * 64;

    for (int it = 0; it < 32; it++) {
        const int m = rowbase + it * 2 + rowslot;
        const float* src = (m < TB) ? (x0 + (size_t)m * TH)
                                    : (g_xt + (size_t)(m - TB) * TH);
        float s0 = 0.f, s1 = 0.f, s2 = 0.f, s3 = 0.f;
#pragma unroll
        for (int s = 0; s < 16; s++) {
            float r = fast_tanh(src[lane + 32 * s]);
            s0 = fmaf(r, cf[s].x, s0);
            s1 = fmaf(r, cf[s].y, s1);
            s2 = fmaf(r, cf[s].z, s2);
            s3 = fmaf(r, cf[s].w, s3);
        }
#pragma unroll
        for (int o = 16; o; o >>= 1) {
            s0 += __shfl_xor_sync(0xffffffffu, s0, o);
            s1 += __shfl_xor_sync(0xffffffffu, s1, o);
            s2 += __shfl_xor_sync(0xffffffffu, s2, o);
            s3 += __shfl_xor_sync(0xffffffffu, s3, o);
        }
        if (lane == 0)
            *(float4*)(g_c1 + (size_t)m * 16 + jg * 4) = make_float4(s0, s1, s2, s3);
    }
}

// ---------------------------------------------------------------------------
// K4: exact parallel weighted scan  q_t = 0.8 q_{t-1} + c1[t,j]*c1[t,j+8]
// One block per (b,j): 256 threads x 4 t each. Local scan -> warp
// Hillis-Steele with decay powers -> cross-warp combine (decay 0.8^128/warp).
// ---------------------------------------------------------------------------
__global__ void __launch_bounds__(256) k_qscan()
{
    const int b    = blockIdx.x >> 3;
    const int j    = blockIdx.x & 7;
    const int tid  = threadIdx.x;
    const int lane = tid & 31;
    const int wid  = tid >> 5;
    __shared__ float wtot[8];

    const int t0 = tid * 4;
    float p[4];
#pragma unroll
    for (int k = 0; k < 4; k++) {
        size_t base = (size_t)((t0 + k) * TB + b) * 16 + j;
        p[k] = g_c1[base] * g_c1[base + 8];
    }

    // thread-local inclusive scan (4 elements)
    float l0 = p[0];
    float l1 = fmaf(0.8f, l0, p[1]);
    float l2 = fmaf(0.8f, l1, p[2]);
    float l3 = fmaf(0.8f, l2, p[3]);

    // warp inclusive scan of carries; per-thread segment decay D1 = 0.8^4
    const float D1 = 0.40960000f;
    float S = l3;
    float dpow = D1;
#pragma unroll
    for (int o = 1; o < 32; o <<= 1) {
        float up = __shfl_up_sync(0xffffffffu, S, o);
        if (lane >= o) S = fmaf(dpow, up, S);
        dpow *= dpow;
    }
    if (lane == 31) wtot[wid] = S;
    __syncthreads();

    // cross-warp prefix: W = sum_{w<wid} wtot[w] * (0.8^128)^(wid-1-w)
    const float DW = 4.0173451106474452e-13f;   // 0.8^128
    float W = 0.f, mult = 1.f;
    for (int w = wid - 1; w >= 0; w--) {
        W = fmaf(mult, wtot[w], W);
        mult *= DW;
    }

    // thread-exclusive prefix E = Sx + W * D1^lane  (Sx = 0 at lane 0)
    float Sx = __shfl_up_sync(0xffffffffu, S, 1);
    if (lane == 0) Sx = 0.f;
    float wdec = 1.f, pb = D1;
    int e = lane;
#pragma unroll
    for (int i = 0; i < 5; i++) {
        if (e & 1) wdec *= pb;
        pb *= pb;
        e >>= 1;
    }
    float E = fmaf(W, wdec, Sx);

    // q_{t0+k} = l_k + E * 0.8^(k+1)
    float f = 0.8f * E;
    float* qp = g_q + ((size_t)b * TT + t0) * 8 + j;
    qp[0]  = l0 + f; f *= 0.8f;
    qp[8]  = l1 + f; f *= 0.8f;
    qp[16] = l2 + f; f *= 0.8f;
    qp[24] = l3 + f;
}

// ---------------------------------------------------------------------------
// K5: fused traj assembly + readout GEMM.
// ---------------------------------------------------------------------------
__global__ void __launch_bounds__(256) k_out(const float* __restrict__ W_out,
                                             const float* __restrict__ b_out,
                                             const float* __restrict__ L,
                                             float* __restrict__ outp,
                                             float* __restrict__ traj,
                                             float* __restrict__ xlast)
{
    __shared__ __align__(16) float at[64 * 64];
    __shared__ __align__(16) float bs2[64 * 64];
    const int bm  = blockIdx.x;
    const int tid = threadIdx.x;
    const int tx = tid & 15;
    const int ty = tid >> 4;
    const int kq = tid & 63;
    const int sw = (kq & 15) << 2;
    const float KC = 0.2f / ((float)TH * (float)TH);

    ull acc[4][2];
#pragma unroll
    for (int i = 0; i < 4; i++) { acc[i][0] = 0ull; acc[i][1] = 0ull; }

    for (int kc = 0; kc < 8; kc++) {
        const int h = kc * 64 + kq;
        float4 L0 = *(const float4*)(L + (size_t)h * TR);
        float4 L1 = *(const float4*)(L + (size_t)h * TR + 4);
        __syncthreads();
#pragma unroll
        for (int s = 0; s < 16; s++) {
            int r = (tid >> 6) + s * 4;
            int m = bm * 64 + r;
            int t = m & (TT - 1);
            int b = m >> 10;
            float xt = g_xt[((size_t)(t * TB + b)) * TH + h];
            const float* qp = g_q + (size_t)m * 8;
            float4 q0 = *(const float4*)qp;
            float4 q1 = *(const float4*)(qp + 4);
            float e = L0.x * q0.x;
            e = fmaf(L0.y, q0.y, e);
            e = fmaf(L0.z, q0.z, e);
            e = fmaf(L0.w, q0.w, e);
            e = fmaf(L1.x, q1.x, e);
            e = fmaf(L1.y, q1.y, e);
            e = fmaf(L1.z, q1.z, e);
            e = fmaf(L1.w, q1.w, e);
            float tv = fmaf(KC, e, xt);
            traj[(size_t)m * TH + h] = tv;
            if (t == TT - 1) xlast[(size_t)b * TH + h] = tv;
            at[kq * 64 + (r ^ sw)]  = acc_tanh(tv);
            bs2[kq * 64 + (r ^ sw)] = W_out[(size_t)r * TH + h];
        }
        __syncthreads();
#pragma unroll
        for (int k = 0; k < 64; k++) {
            int swk = (k & 15) << 2;
            float4 a = *(const float4*)&at[k * 64 + ((ty * 4) ^ swk)];
            ulonglong2 w2 = *(const ulonglong2*)&bs2[k * 64 + ((tx * 4) ^ swk)];
            ull d0 = dup2(a.x), d1 = dup2(a.y), d2 = dup2(a.z), d3 = dup2(a.w);
            fma2(acc[0][0], d0, w2.x); fma2(acc[0][1], d0, w2.y);
            fma2(acc[1][0], d1, w2.x); fma2(acc[1][1], d1, w2.y);
            fma2(acc[2][0], d2, w2.x); fma2(acc[2][1], d2, w2.y);
            fma2(acc[3][0], d3, w2.x); fma2(acc[3][1], d3, w2.y);
        }
    }

    const int o0 = tx * 4;
    float4 bias = *(const float4*)&b_out[o0];
#pragma unroll
    for (int i = 0; i < 4; i++) {
        int m = bm * 64 + ty * 4 + i;
        float v0, v1, v2, v3;
        unpack2(acc[i][0], v0, v1);
        unpack2(acc[i][1], v2, v3);
        float4 o;
        o.x = v0 + bias.x; o.y = v1 + bias.y;
        o.z = v2 + bias.z; o.w = v3 + bias.w;
        *(float4*)&outp[(size_t)m * TO + o0] = o;
    }
}

// ---------------------------------------------------------------------------
// Launcher. Inputs: u, x0, noise, L, M, N, W_in, b_in, W_out, b_out.
// Output: [output | x_last | traj].
// ---------------------------------------------------------------------------
extern "C" void kernel_launch(void* const* d_in, const int* in_sizes, int n_in,
                              void* d_out, int out_size)
{
    (void)in_sizes; (void)n_in; (void)out_size;
    const float* u     = (const float*)d_in[0];
    const float* x0    = (const float*)d_in[1];
    const float* noise = (const float*)d_in[2];
    const float* L     = (const float*)d_in[3];
    const float* Mw    = (const float*)d_in[4];
    const float* Nw    = (const float*)d_in[5];
    const float* W_in  = (const float*)d_in[6];
    const float* b_in  = (const float*)d_in[7];
    const float* W_out = (const float*)d_in[8];
    const float* b_out = (const float*)d_in[9];

    float* outp  = (float*)d_out;
    float* xlast = outp + (size_t)TB * TT * TO;
    float* traj  = xlast + (size_t)TB * TH;

    dim3 g1(TT, TH / 64);
    k_inp<<<g1, 256>>>(u, W_in, b_in, noise);
    k_scanA<<<dim3(128, 4), 256>>>(x0);
    k_rec<<<1024, 256>>>(x0, Mw, Nw);
    k_qscan<<<512, 256>>>();
    k_out<<<(TB * TT) / 64, 256>>>(W_out, b_out, L, outp, traj, xlast);
}